// round 15
// baseline (speedup 1.0000x reference)
#include <cuda_runtime.h>
#include <math.h>
#include <float.h>
#include <limits.h>

#define LSIG 8192
#define N2   4096
#define NTH  512
#define NWARP 16
#define SRATE 30.0f

// quarter-wave table: (cos, sin)(2*pi*k/8192) for k = 0..1024
__device__ float2 g_tab[1025];

__global__ void tab_init_kernel() {
    int k = blockIdx.x * blockDim.x + threadIdx.x;
    if (k <= 1024) {
        double a = 2.0 * 3.14159265358979323846 * (double)k / 8192.0;
        g_tab[k] = make_float2((float)cos(a), (float)sin(a));
    }
}

// sqrt on the FMA pipe (avoid MUFU bottleneck). Safe at x == 0.
__device__ __forceinline__ float fast_sqrt(float x) {
    float xh = 0.5f * x;
    int i = __float_as_int(x);
    i = 0x5f375a86 - (i >> 1);
    float y = __int_as_float(i);
    y = y * (1.5f - xh * y * y);
    y = y * (1.5f - xh * y * y);
    return x * y;
}

// XOR bank swizzle on complex index (FFT stages only).
__device__ __forceinline__ int swz(int a) { return a ^ ((a >> 4) & 15); }

// e^{-2*pi*i*q/8192} for q in [0, 2048), via quarter-wave table
__device__ __forceinline__ float2 Wq(const float2* __restrict__ tab, int q) {
    if (q <= 1024) {
        float2 t = tab[q];
        return make_float2(t.x, -t.y);
    }
    float2 t = tab[2048 - q];
    return make_float2(t.y, -t.x);
}

__device__ __forceinline__ float2 cmul(float2 a, float2 b) {
    return make_float2(fmaf(a.x, b.x, -(a.y * b.y)), fmaf(a.x, b.y, a.y * b.x));
}
__device__ __forceinline__ float2 cadd(float2 a, float2 b) {
    return make_float2(a.x + b.x, a.y + b.y);
}
__device__ __forceinline__ float2 csub(float2 a, float2 b) {
    return make_float2(a.x - b.x, a.y - b.y);
}
// i * a
__device__ __forceinline__ float2 jmul(float2 a) { return make_float2(-a.y, a.x); }

// One radix-8 Stockham stage. S = 8^t. NATREAD: read natural layout (stage 0).
// TW: apply twiddles (false for last stage where p == 0).
template <int S, bool TW, bool NATREAD>
__device__ __forceinline__ void r8_stage(const float2* __restrict__ cur,
                                         float2* __restrict__ nxt,
                                         const float2* __restrict__ tab,
                                         int i) {
    const int base = NATREAD ? i : swz(i);
    float2 a0 = cur[base];
    float2 a1 = cur[base + 512];
    float2 a2 = cur[base + 1024];
    float2 a3 = cur[base + 1536];
    float2 a4 = cur[base + 2048];
    float2 a5 = cur[base + 2560];
    float2 a6 = cur[base + 3072];
    float2 a7 = cur[base + 3584];

    float2 ta = cadd(a0, a4), tb = csub(a0, a4);
    float2 tc = cadd(a2, a6), td = jmul(csub(a2, a6));
    float2 E0 = cadd(ta, tc);
    float2 E1 = csub(tb, td);
    float2 E2 = csub(ta, tc);
    float2 E3 = cadd(tb, td);
    ta = cadd(a1, a5); tb = csub(a1, a5);
    tc = cadd(a3, a7); td = jmul(csub(a3, a7));
    float2 O0 = cadd(ta, tc);
    float2 O1 = csub(tb, td);
    float2 O2 = csub(ta, tc);
    float2 O3 = cadd(tb, td);

    const float C = 0.70710678118654752f;
    float2 R1 = make_float2(C * (O1.x + O1.y), C * (O1.y - O1.x));
    float2 R2 = make_float2(O2.y, -O2.x);
    float2 R3 = make_float2(C * (O3.y - O3.x), -C * (O3.x + O3.y));

    if (TW) {
        const int ps = i & ~(S - 1);
        const int wb = i + 7 * ps;
        float2 t1 = tab[ps << 1];
        float2 w1 = make_float2(t1.x, -t1.y);
        float2 w2 = cmul(w1, w1);
        float2 w4 = cmul(w2, w2);

        nxt[swz(wb)] = cadd(E0, O0);
        nxt[swz(wb + 4 * S)] = cmul(w4, csub(E0, O0));
        float2 wr = w1;
        nxt[swz(wb + S)] = cmul(wr, cadd(E1, R1));
        nxt[swz(wb + 5 * S)] = cmul(cmul(wr, w4), csub(E1, R1));
        wr = w2;
        nxt[swz(wb + 2 * S)] = cmul(wr, cadd(E2, R2));
        nxt[swz(wb + 6 * S)] = cmul(cmul(wr, w4), csub(E2, R2));
        wr = cmul(w2, w1);
        nxt[swz(wb + 3 * S)] = cmul(wr, cadd(E3, R3));
        nxt[swz(wb + 7 * S)] = cmul(cmul(wr, w4), csub(E3, R3));
    } else {
        const int sb = swz(i);
        nxt[sb] = cadd(E0, O0);
        nxt[sb + 512] = cadd(E1, R1);
        nxt[sb + 1024] = cadd(E2, R2);
        nxt[sb + 1536] = cadd(E3, R3);
        nxt[sb + 2048] = csub(E0, O0);
        nxt[sb + 2560] = csub(E1, R1);
        nxt[sb + 3072] = csub(E2, R2);
        nxt[sb + 3584] = csub(E3, R3);
    }
}

// two-smallest insertion (order-insensitive)
#define INS2(va, vb, idx)                         \
    do {                                          \
        if ((idx) < (va)) { (vb) = (va); (va) = (idx); } \
        else if ((idx) < (vb)) (vb) = (idx);      \
    } while (0)

// dynamic smem: bufA[4096] | bufB[4096] | tab[1025]  (float2) = 73736 bytes
extern __shared__ float2 s_dyn2[];

__global__ __launch_bounds__(NTH, 3)
void feat_kernel(const float* __restrict__ x, float* __restrict__ out) {
    float2* bufA = s_dyn2;
    float2* bufB = s_dyn2 + N2;
    float2* tab = s_dyn2 + 2 * N2;

    __shared__ float fp1[4][NWARP];
    __shared__ int ip1[6][NWARP];
    __shared__ float fres[4];
    __shared__ int ires[6];
    __shared__ float s_S[4];
    __shared__ int s_lr[2];
    __shared__ float s_pts[4];

    const int tid = threadIdx.x;
    const int lane = tid & 31;
    const int wrp = tid >> 5;
    const float2* __restrict__ sig2 =
        (const float2*)(x + (size_t)blockIdx.x * LSIG);

#pragma unroll
    for (int i = tid; i < 1025; i += NTH) tab[i] = g_tab[i];

    // ---- fused pass: global load + stats + interior peak/valley ----
    float mx = -FLT_MAX, mn = FLT_MAX, sum = 0.0f, ssq = 0.0f;
    int np = 0, nv = 0, p0 = INT_MAX, va = INT_MAX, vb = INT_MAX, vlast = -1;
#pragma unroll
    for (int k = 0; k < N2 / NTH; k++) {
        int n = tid + k * NTH;
        float2 v = sig2[n];
        mx = fmaxf(mx, fmaxf(v.x, v.y));
        mn = fminf(mn, fminf(v.x, v.y));
        sum += v.x + v.y;
        ssq = fmaf(v.x, v.x, ssq);
        ssq = fmaf(v.y, v.y, ssq);
        bufA[n] = v;
        float pl = __shfl_up_sync(0xffffffffu, v.y, 1);
        float nr = __shfl_down_sync(0xffffffffu, v.x, 1);
        int ie = 2 * n, io = ie + 1;
        bool de = (lane != 0) && (n > 0);
        bool dq = (lane != 31) && (n < N2 - 1);
        if (de && v.x > pl && v.x > v.y) { np++; p0 = min(p0, ie); }
        if (de && v.x < pl && v.x < v.y) { nv++; vlast = max(vlast, ie); INS2(va, vb, ie); }
        if (dq && v.y > v.x && v.y > nr) { np++; p0 = min(p0, io); }
        if (dq && v.y < v.x && v.y < nr) { nv++; vlast = max(vlast, io); INS2(va, vb, io); }
    }
    __syncthreads();

    const float* __restrict__ re = (const float*)bufA;

    // ---- warp-boundary fix-up (2 elements per warp per iteration) ----
    if (lane == 0) {
#pragma unroll
        for (int k = 0; k < N2 / NTH; k++) {
            int n = tid + k * NTH;
            if (n > 0) {
                int ie = 2 * n;
                float a = re[ie - 1], v = re[ie], c = re[ie + 1];
                if (v > a && v > c) { np++; p0 = min(p0, ie); }
                if (v < a && v < c) { nv++; vlast = max(vlast, ie); INS2(va, vb, ie); }
            }
        }
    } else if (lane == 31) {
#pragma unroll
        for (int k = 0; k < N2 / NTH; k++) {
            int n = tid + k * NTH;
            if (n < N2 - 1) {
                int io = 2 * n + 1;
                float a = re[io - 1], v = re[io], c = re[io + 1];
                if (v > a && v > c) { np++; p0 = min(p0, io); }
                if (v < a && v < c) { nv++; vlast = max(vlast, io); INS2(va, vb, io); }
            }
        }
    }

    // ---- batched block reduction: all phase-1 quantities, 2 barriers ----
#pragma unroll
    for (int o = 16; o; o >>= 1) {
        mx = fmaxf(mx, __shfl_down_sync(0xffffffffu, mx, o));
        mn = fminf(mn, __shfl_down_sync(0xffffffffu, mn, o));
        sum += __shfl_down_sync(0xffffffffu, sum, o);
        ssq += __shfl_down_sync(0xffffffffu, ssq, o);
        np += __shfl_down_sync(0xffffffffu, np, o);
        nv += __shfl_down_sync(0xffffffffu, nv, o);
        p0 = min(p0, __shfl_down_sync(0xffffffffu, p0, o));
        vlast = max(vlast, __shfl_down_sync(0xffffffffu, vlast, o));
        int oa = __shfl_down_sync(0xffffffffu, va, o);
        int ob = __shfl_down_sync(0xffffffffu, vb, o);
        int m1 = min(va, oa);
        vb = min(max(va, oa), min(vb, ob));
        va = m1;
    }
    if (lane == 0) {
        fp1[0][wrp] = mx; fp1[1][wrp] = mn; fp1[2][wrp] = sum; fp1[3][wrp] = ssq;
        ip1[0][wrp] = np; ip1[1][wrp] = nv; ip1[2][wrp] = p0; ip1[3][wrp] = vlast;
        ip1[4][wrp] = va; ip1[5][wrp] = vb;
    }
    __syncthreads();
    if (wrp < 4) {
        float ident = (wrp == 0) ? -FLT_MAX : (wrp == 1) ? FLT_MAX : 0.0f;
        float v = (lane < NWARP) ? fp1[wrp][lane] : ident;
#pragma unroll
        for (int o = 8; o; o >>= 1) {
            float ov = __shfl_down_sync(0xffffffffu, v, o);
            v = (wrp == 0) ? fmaxf(v, ov) : (wrp == 1) ? fminf(v, ov) : (v + ov);
        }
        if (lane == 0) fres[wrp] = v;
    } else if (wrp < 8) {
        int q = wrp - 4;  // 0:np 1:nv 2:p0(min) 3:vlast(max)
        int ident = (q < 2) ? 0 : (q == 2) ? INT_MAX : INT_MIN;
        int v = (lane < NWARP) ? ip1[q][lane] : ident;
#pragma unroll
        for (int o = 8; o; o >>= 1) {
            int ov = __shfl_down_sync(0xffffffffu, v, o);
            v = (q < 2) ? (v + ov) : (q == 2) ? min(v, ov) : max(v, ov);
        }
        if (lane == 0) ires[q] = v;
    } else if (wrp == 8) {
        int a = (lane < NWARP) ? ip1[4][lane] : INT_MAX;
        int b = (lane < NWARP) ? ip1[5][lane] : INT_MAX;
#pragma unroll
        for (int o = 8; o; o >>= 1) {
            int oa = __shfl_down_sync(0xffffffffu, a, o);
            int ob = __shfl_down_sync(0xffffffffu, b, o);
            int m1 = min(a, oa);
            b = min(max(a, oa), min(b, ob));
            a = m1;
        }
        if (lane == 0) { ires[4] = a; ires[5] = b; }
    }
    __syncthreads();
    mx = fres[0]; mn = fres[1]; sum = fres[2]; ssq = fres[3];
    np = ires[0]; nv = ires[1]; p0 = ires[2]; vlast = ires[3];
    va = ires[4]; vb = ires[5];

    const bool valid = (np >= 1) && (nv >= 2);
    const int P0 = valid ? p0 : 0;
    const int V0 = valid ? va : 0;
    const int V1 = valid ? vb : 0;
    const int VL = valid ? vlast : 0;

    const float sp0 = re[P0], sv0 = re[V0];
    const float PH = sp0 - sv0;
    const float hh = (PH + sv0) * 0.5f;

    // thresholds for masked prefix sums
    const int T2 = max(V1 - 1, P0);
    const int T3 = max(VL - 1, V0);
    if (tid == 0) {
        s_pts[0] = re[0];
        s_pts[1] = re[max(P0 - 1, V0)];  // sig[T1]
        s_pts[2] = re[T2];
        s_pts[3] = re[T3];
    }

    // ---- phase 2: masked prefix sums + half-height width (float4 pass) ----
    float s0 = 0.0f, s1 = 0.0f, s2 = 0.0f, s3 = 0.0f;
    int li = INT_MAX, ri = -1;
    {
        const float4* __restrict__ b4 = (const float4*)bufA;
#pragma unroll
        for (int k = 0; k < 4; k++) {
            int t = tid + k * NTH;
            float4 q = b4[t];
            int base = 4 * t;
#pragma unroll
            for (int j = 0; j < 4; j++) {
                int idx = base + j;
                float val = (j == 0) ? q.x : (j == 1) ? q.y : (j == 2) ? q.z : q.w;
                if (idx <= V0) s0 += val;
                if (idx <= P0) s1 += val;
                if (idx <= T2) s2 += val;
                if (idx <= T3) s3 += val;
                if (val >= hh) {
                    if (idx >= V0 && idx < P0) li = min(li, idx);
                    if (idx > V0 && idx <= P0) ri = max(ri, idx);
                }
            }
        }
    }
    // reduce phase-2 quantities now (frees registers before FFT)
#pragma unroll
    for (int o = 16; o; o >>= 1) {
        s0 += __shfl_down_sync(0xffffffffu, s0, o);
        s1 += __shfl_down_sync(0xffffffffu, s1, o);
        s2 += __shfl_down_sync(0xffffffffu, s2, o);
        s3 += __shfl_down_sync(0xffffffffu, s3, o);
        li = min(li, __shfl_down_sync(0xffffffffu, li, o));
        ri = max(ri, __shfl_down_sync(0xffffffffu, ri, o));
    }
    if (lane == 0) {
        fp1[0][wrp] = s0; fp1[1][wrp] = s1; fp1[2][wrp] = s2; fp1[3][wrp] = s3;
        ip1[0][wrp] = li; ip1[1][wrp] = ri;
    }
    __syncthreads();
    if (wrp < 4) {
        float v = (lane < NWARP) ? fp1[wrp][lane] : 0.0f;
#pragma unroll
        for (int o = 8; o; o >>= 1) v += __shfl_down_sync(0xffffffffu, v, o);
        if (lane == 0) s_S[wrp] = v;
    } else if (wrp == 4) {
        int v = (lane < NWARP) ? ip1[0][lane] : INT_MAX;
#pragma unroll
        for (int o = 8; o; o >>= 1) v = min(v, __shfl_down_sync(0xffffffffu, v, o));
        if (lane == 0) s_lr[0] = v;
    } else if (wrp == 5) {
        int v = (lane < NWARP) ? ip1[1][lane] : INT_MIN;
#pragma unroll
        for (int o = 8; o; o >>= 1) v = max(v, __shfl_down_sync(0xffffffffu, v, o));
        if (lane == 0) s_lr[1] = v;
    }
    __syncthreads();

    // ---- 4096-point Stockham radix-8 FFT, 4 stages, natural-order output ----
    r8_stage<1, true, true>(bufA, bufB, tab, tid);
    __syncthreads();
    r8_stage<8, true, false>(bufB, bufA, tab, tid);
    __syncthreads();
    r8_stage<64, true, false>(bufA, bufB, tab, tid);
    __syncthreads();
    r8_stage<512, false, false>(bufB, bufA, tab, tid);
    __syncthreads();
    const float2* __restrict__ cur = bufA;

    // ---- real-FFT unpack + magnitude sum (Hermitian-halved) ----
    float ms = 0.0f;
#pragma unroll
    for (int k0 = 0; k0 < N2 / NTH; k0++) {
        int k = tid + k0 * NTH;
        int kp = (N2 - k) & (N2 - 1);
        float2 Zk = cur[swz(k)];
        float2 Zp = cur[swz(kp)];
        float Er = 0.5f * (Zk.x + Zp.x);
        float Ei = 0.5f * (Zk.y - Zp.y);
        float Or = 0.5f * (Zk.y + Zp.y);
        float Oi = 0.5f * (Zp.x - Zk.x);
        float2 w;
        if (k0 < 2) {
            float2 t = tab[k];
            w = make_float2(t.x, -t.y);
        } else if (k0 < 4) {
            w = Wq(tab, k);
        } else {
            float2 u = Wq(tab, k - 2048);
            w = make_float2(u.y, -u.x);
        }
        float2 wo = cmul(w, make_float2(Or, Oi));
        if (k == 0) {
            ms += fabsf(Er + Or) + fabsf(Er - Or);  // |X[0]| + |X[4096]|
        } else {
            float xr = Er + wo.x, xi = Ei + wo.y;
            ms += 2.0f * fast_sqrt(fmaf(xr, xr, xi * xi));
        }
    }
#pragma unroll
    for (int o = 16; o; o >>= 1) ms += __shfl_down_sync(0xffffffffu, ms, o);
    if (lane == 0) fp1[0][wrp] = ms;
    __syncthreads();
    if (wrp == 0) {
        float v = (lane < NWARP) ? fp1[0][lane] : 0.0f;
#pragma unroll
        for (int o = 8; o; o >>= 1) v += __shfl_down_sync(0xffffffffu, v, o);
        if (lane == 0) {
            const float hs = 0.5f / SRATE;
            float S_T0 = s_S[0], S_P0 = s_S[1], S_T2 = s_S[2], S_T3 = s_S[3];
            float sig0 = s_pts[0], rT1 = s_pts[1], rT2 = s_pts[2], rT3 = s_pts[3];
            float S_T1 = (P0 > V0) ? (S_P0 - sp0) : S_T0;
            // C(j) = hs * (2*S[j] - sig[j] - sig[0])
            float C_T0 = hs * (2.0f * S_T0 - sv0 - sig0);
            float C_P0 = hs * (2.0f * S_P0 - sp0 - sig0);
            float C_T1 = hs * (2.0f * S_T1 - rT1 - sig0);
            float C_T2 = hs * (2.0f * S_T2 - rT2 - sig0);
            float C_T3 = hs * (2.0f * S_T3 - rT3 - sig0);
            float pa = C_T3 - C_T0;
            float a2 = C_T2 - C_P0;
            float a1 = C_T1 - C_T0;
            int lii = s_lr[0], rii = s_lr[1];
            if (lii == INT_MAX) lii = V0;
            if (rii == -1) rii = P0;
            float pwhh = (float)(rii - lii) * (1.0f / SRATE);

            float fftm = v * (1.0f / (float)LSIG);
            float mean = sum * (1.0f / (float)LSIG);
            float var = (ssq - sum * mean) * (1.0f / (float)(LSIG - 1));
            float* o_ = out + (size_t)blockIdx.x * 10;
            o_[0] = mx;
            o_[1] = mx - mn;
            o_[2] = var;
            o_[3] = sqrtf(var);
            o_[4] = fftm;
            o_[5] = valid ? pa : 0.0f;
            o_[6] = valid ? a2 : 0.0f;
            o_[7] = valid ? PH : 0.0f;
            o_[8] = valid ? a1 : 0.0f;
            o_[9] = valid ? pwhh : 0.0f;
        }
    }
}

extern "C" void kernel_launch(void* const* d_in, const int* in_sizes, int n_in,
                              void* d_out, int out_size) {
    const float* x = (const float*)d_in[0];
    float* out = (float*)d_out;
    int nrow = in_sizes[0] / LSIG;

    (void)n_in; (void)out_size;

    const int smem = (2 * N2 + 1025) * (int)sizeof(float2);  // 73736
    cudaFuncSetAttribute(feat_kernel, cudaFuncAttributeMaxDynamicSharedMemorySize, smem);

    tab_init_kernel<<<5, 256>>>();
    feat_kernel<<<nrow, NTH, smem>>>(x, out);
}

// round 16
// speedup vs baseline: 1.0034x; 1.0034x over previous
#include <cuda_runtime.h>
#include <math.h>
#include <float.h>
#include <limits.h>

#define LSIG 8192
#define N2   4096
#define NTH  512
#define NWARP 16
#define SRATE 30.0f

// quarter-wave table: (cos, sin)(2*pi*k/8192) for k = 0..1024
__device__ float2 g_tab[1025];

__global__ void tab_init_kernel() {
    int k = blockIdx.x * blockDim.x + threadIdx.x;
    if (k <= 1024) {
        double a = 2.0 * 3.14159265358979323846 * (double)k / 8192.0;
        g_tab[k] = make_float2((float)cos(a), (float)sin(a));
    }
}

// sqrt on the FMA pipe (avoid MUFU bottleneck). Safe at x == 0.
__device__ __forceinline__ float fast_sqrt(float x) {
    float xh = 0.5f * x;
    int i = __float_as_int(x);
    i = 0x5f375a86 - (i >> 1);
    float y = __int_as_float(i);
    y = y * (1.5f - xh * y * y);
    y = y * (1.5f - xh * y * y);
    return x * y;
}

// XOR bank swizzle on complex index (FFT stages only).
__device__ __forceinline__ int swz(int a) { return a ^ ((a >> 4) & 15); }

// e^{-2*pi*i*q/8192} for q in [0, 2048), via quarter-wave table
__device__ __forceinline__ float2 Wq(const float2* __restrict__ tab, int q) {
    if (q <= 1024) {
        float2 t = tab[q];
        return make_float2(t.x, -t.y);
    }
    float2 t = tab[2048 - q];
    return make_float2(t.y, -t.x);
}

__device__ __forceinline__ float2 cmul(float2 a, float2 b) {
    return make_float2(fmaf(a.x, b.x, -(a.y * b.y)), fmaf(a.x, b.y, a.y * b.x));
}
__device__ __forceinline__ float2 cadd(float2 a, float2 b) {
    return make_float2(a.x + b.x, a.y + b.y);
}
__device__ __forceinline__ float2 csub(float2 a, float2 b) {
    return make_float2(a.x - b.x, a.y - b.y);
}
// i * a
__device__ __forceinline__ float2 jmul(float2 a) { return make_float2(-a.y, a.x); }

// One radix-8 Stockham stage. S = 8^t. NATREAD: read natural layout (stage 0).
// TW: apply twiddles (false for last stage where p == 0).
template <int S, bool TW, bool NATREAD>
__device__ __forceinline__ void r8_stage(const float2* __restrict__ cur,
                                         float2* __restrict__ nxt,
                                         const float2* __restrict__ tab,
                                         int i) {
    const int base = NATREAD ? i : swz(i);
    float2 a0 = cur[base];
    float2 a1 = cur[base + 512];
    float2 a2 = cur[base + 1024];
    float2 a3 = cur[base + 1536];
    float2 a4 = cur[base + 2048];
    float2 a5 = cur[base + 2560];
    float2 a6 = cur[base + 3072];
    float2 a7 = cur[base + 3584];

    float2 ta = cadd(a0, a4), tb = csub(a0, a4);
    float2 tc = cadd(a2, a6), td = jmul(csub(a2, a6));
    float2 E0 = cadd(ta, tc);
    float2 E1 = csub(tb, td);
    float2 E2 = csub(ta, tc);
    float2 E3 = cadd(tb, td);
    ta = cadd(a1, a5); tb = csub(a1, a5);
    tc = cadd(a3, a7); td = jmul(csub(a3, a7));
    float2 O0 = cadd(ta, tc);
    float2 O1 = csub(tb, td);
    float2 O2 = csub(ta, tc);
    float2 O3 = cadd(tb, td);

    const float C = 0.70710678118654752f;
    float2 R1 = make_float2(C * (O1.x + O1.y), C * (O1.y - O1.x));
    float2 R2 = make_float2(O2.y, -O2.x);
    float2 R3 = make_float2(C * (O3.y - O3.x), -C * (O3.x + O3.y));

    if (TW) {
        const int ps = i & ~(S - 1);
        const int wb = i + 7 * ps;
        float2 t1 = tab[ps << 1];
        float2 w1 = make_float2(t1.x, -t1.y);
        float2 w2 = cmul(w1, w1);
        float2 w4 = cmul(w2, w2);

        nxt[swz(wb)] = cadd(E0, O0);
        nxt[swz(wb + 4 * S)] = cmul(w4, csub(E0, O0));
        float2 wr = w1;
        nxt[swz(wb + S)] = cmul(wr, cadd(E1, R1));
        nxt[swz(wb + 5 * S)] = cmul(cmul(wr, w4), csub(E1, R1));
        wr = w2;
        nxt[swz(wb + 2 * S)] = cmul(wr, cadd(E2, R2));
        nxt[swz(wb + 6 * S)] = cmul(cmul(wr, w4), csub(E2, R2));
        wr = cmul(w2, w1);
        nxt[swz(wb + 3 * S)] = cmul(wr, cadd(E3, R3));
        nxt[swz(wb + 7 * S)] = cmul(cmul(wr, w4), csub(E3, R3));
    } else {
        const int sb = swz(i);
        nxt[sb] = cadd(E0, O0);
        nxt[sb + 512] = cadd(E1, R1);
        nxt[sb + 1024] = cadd(E2, R2);
        nxt[sb + 1536] = cadd(E3, R3);
        nxt[sb + 2048] = csub(E0, O0);
        nxt[sb + 2560] = csub(E1, R1);
        nxt[sb + 3072] = csub(E2, R2);
        nxt[sb + 3584] = csub(E3, R3);
    }
}

// two-smallest insertion (order-insensitive)
#define INS2(va, vb, idx)                         \
    do {                                          \
        if ((idx) < (va)) { (vb) = (va); (va) = (idx); } \
        else if ((idx) < (vb)) (vb) = (idx);      \
    } while (0)

// dynamic smem: bufA[4096] | bufB[4096] | tab[1025]  (float2) = 73736 bytes
extern __shared__ float2 s_dyn2[];

__global__ __launch_bounds__(NTH, 3)
void feat_kernel(const float* __restrict__ x, float* __restrict__ out) {
    float2* bufA = s_dyn2;
    float2* bufB = s_dyn2 + N2;
    float2* tab = s_dyn2 + 2 * N2;

    __shared__ float fp1[4][NWARP];
    __shared__ int ip1[6][NWARP];
    __shared__ float fres[4];
    __shared__ int ires[6];
    __shared__ float s_S[4];
    __shared__ int s_lr[2];
    __shared__ float s_pts[4];

    const int tid = threadIdx.x;
    const int lane = tid & 31;
    const int wrp = tid >> 5;
    const float2* __restrict__ sig2 =
        (const float2*)(x + (size_t)blockIdx.x * LSIG);

#pragma unroll
    for (int i = tid; i < 1025; i += NTH) tab[i] = g_tab[i];

    // ---- fused pass: global load + stats + interior peak/valley ----
    float mx = -FLT_MAX, mn = FLT_MAX, sum = 0.0f, ssq = 0.0f;
    int np = 0, nv = 0, p0 = INT_MAX, va = INT_MAX, vb = INT_MAX, vlast = -1;
#pragma unroll
    for (int k = 0; k < N2 / NTH; k++) {
        int n = tid + k * NTH;
        float2 v = sig2[n];
        mx = fmaxf(mx, fmaxf(v.x, v.y));
        mn = fminf(mn, fminf(v.x, v.y));
        sum += v.x + v.y;
        ssq = fmaf(v.x, v.x, ssq);
        ssq = fmaf(v.y, v.y, ssq);
        bufA[n] = v;
        float pl = __shfl_up_sync(0xffffffffu, v.y, 1);
        float nr = __shfl_down_sync(0xffffffffu, v.x, 1);
        int ie = 2 * n, io = ie + 1;
        bool de = (lane != 0) && (n > 0);
        bool dq = (lane != 31) && (n < N2 - 1);
        if (de && v.x > pl && v.x > v.y) { np++; p0 = min(p0, ie); }
        if (de && v.x < pl && v.x < v.y) { nv++; vlast = max(vlast, ie); INS2(va, vb, ie); }
        if (dq && v.y > v.x && v.y > nr) { np++; p0 = min(p0, io); }
        if (dq && v.y < v.x && v.y < nr) { nv++; vlast = max(vlast, io); INS2(va, vb, io); }
    }
    __syncthreads();

    const float* __restrict__ re = (const float*)bufA;

    // ---- warp-boundary fix-up (2 elements per warp per iteration) ----
    if (lane == 0) {
#pragma unroll
        for (int k = 0; k < N2 / NTH; k++) {
            int n = tid + k * NTH;
            if (n > 0) {
                int ie = 2 * n;
                float a = re[ie - 1], v = re[ie], c = re[ie + 1];
                if (v > a && v > c) { np++; p0 = min(p0, ie); }
                if (v < a && v < c) { nv++; vlast = max(vlast, ie); INS2(va, vb, ie); }
            }
        }
    } else if (lane == 31) {
#pragma unroll
        for (int k = 0; k < N2 / NTH; k++) {
            int n = tid + k * NTH;
            if (n < N2 - 1) {
                int io = 2 * n + 1;
                float a = re[io - 1], v = re[io], c = re[io + 1];
                if (v > a && v > c) { np++; p0 = min(p0, io); }
                if (v < a && v < c) { nv++; vlast = max(vlast, io); INS2(va, vb, io); }
            }
        }
    }

    // ---- batched block reduction: all phase-1 quantities, 2 barriers ----
#pragma unroll
    for (int o = 16; o; o >>= 1) {
        mx = fmaxf(mx, __shfl_down_sync(0xffffffffu, mx, o));
        mn = fminf(mn, __shfl_down_sync(0xffffffffu, mn, o));
        sum += __shfl_down_sync(0xffffffffu, sum, o);
        ssq += __shfl_down_sync(0xffffffffu, ssq, o);
        np += __shfl_down_sync(0xffffffffu, np, o);
        nv += __shfl_down_sync(0xffffffffu, nv, o);
        p0 = min(p0, __shfl_down_sync(0xffffffffu, p0, o));
        vlast = max(vlast, __shfl_down_sync(0xffffffffu, vlast, o));
        int oa = __shfl_down_sync(0xffffffffu, va, o);
        int ob = __shfl_down_sync(0xffffffffu, vb, o);
        int m1 = min(va, oa);
        vb = min(max(va, oa), min(vb, ob));
        va = m1;
    }
    if (lane == 0) {
        fp1[0][wrp] = mx; fp1[1][wrp] = mn; fp1[2][wrp] = sum; fp1[3][wrp] = ssq;
        ip1[0][wrp] = np; ip1[1][wrp] = nv; ip1[2][wrp] = p0; ip1[3][wrp] = vlast;
        ip1[4][wrp] = va; ip1[5][wrp] = vb;
    }
    __syncthreads();
    if (wrp < 4) {
        float ident = (wrp == 0) ? -FLT_MAX : (wrp == 1) ? FLT_MAX : 0.0f;
        float v = (lane < NWARP) ? fp1[wrp][lane] : ident;
#pragma unroll
        for (int o = 8; o; o >>= 1) {
            float ov = __shfl_down_sync(0xffffffffu, v, o);
            v = (wrp == 0) ? fmaxf(v, ov) : (wrp == 1) ? fminf(v, ov) : (v + ov);
        }
        if (lane == 0) fres[wrp] = v;
    } else if (wrp < 8) {
        int q = wrp - 4;  // 0:np 1:nv 2:p0(min) 3:vlast(max)
        int ident = (q < 2) ? 0 : (q == 2) ? INT_MAX : INT_MIN;
        int v = (lane < NWARP) ? ip1[q][lane] : ident;
#pragma unroll
        for (int o = 8; o; o >>= 1) {
            int ov = __shfl_down_sync(0xffffffffu, v, o);
            v = (q < 2) ? (v + ov) : (q == 2) ? min(v, ov) : max(v, ov);
        }
        if (lane == 0) ires[q] = v;
    } else if (wrp == 8) {
        int a = (lane < NWARP) ? ip1[4][lane] : INT_MAX;
        int b = (lane < NWARP) ? ip1[5][lane] : INT_MAX;
#pragma unroll
        for (int o = 8; o; o >>= 1) {
            int oa = __shfl_down_sync(0xffffffffu, a, o);
            int ob = __shfl_down_sync(0xffffffffu, b, o);
            int m1 = min(a, oa);
            b = min(max(a, oa), min(b, ob));
            a = m1;
        }
        if (lane == 0) { ires[4] = a; ires[5] = b; }
    }
    __syncthreads();
    mx = fres[0]; mn = fres[1]; sum = fres[2]; ssq = fres[3];
    np = ires[0]; nv = ires[1]; p0 = ires[2]; vlast = ires[3];
    va = ires[4]; vb = ires[5];

    const bool valid = (np >= 1) && (nv >= 2);
    const int P0 = valid ? p0 : 0;
    const int V0 = valid ? va : 0;
    const int V1 = valid ? vb : 0;
    const int VL = valid ? vlast : 0;

    const float sp0 = re[P0], sv0 = re[V0];
    const float PH = sp0 - sv0;
    const float hh = (PH + sv0) * 0.5f;

    // thresholds for masked prefix sums
    const int T2 = max(V1 - 1, P0);
    const int T3 = max(VL - 1, V0);
    if (tid == 0) {
        s_pts[0] = re[0];
        s_pts[1] = re[max(P0 - 1, V0)];  // sig[T1]
        s_pts[2] = re[T2];
        s_pts[3] = re[T3];
    }

    // ---- phase 2: masked prefix sums + half-height width (float4 pass) ----
    float s0 = 0.0f, s1 = 0.0f, s2 = 0.0f, s3 = 0.0f;
    int li = INT_MAX, ri = -1;
    {
        const float4* __restrict__ b4 = (const float4*)bufA;
#pragma unroll
        for (int k = 0; k < 4; k++) {
            int t = tid + k * NTH;
            float4 q = b4[t];
            int base = 4 * t;
#pragma unroll
            for (int j = 0; j < 4; j++) {
                int idx = base + j;
                float val = (j == 0) ? q.x : (j == 1) ? q.y : (j == 2) ? q.z : q.w;
                if (idx <= V0) s0 += val;
                if (idx <= P0) s1 += val;
                if (idx <= T2) s2 += val;
                if (idx <= T3) s3 += val;
                if (val >= hh) {
                    if (idx >= V0 && idx < P0) li = min(li, idx);
                    if (idx > V0 && idx <= P0) ri = max(ri, idx);
                }
            }
        }
    }
    // reduce phase-2 quantities now (frees registers before FFT)
#pragma unroll
    for (int o = 16; o; o >>= 1) {
        s0 += __shfl_down_sync(0xffffffffu, s0, o);
        s1 += __shfl_down_sync(0xffffffffu, s1, o);
        s2 += __shfl_down_sync(0xffffffffu, s2, o);
        s3 += __shfl_down_sync(0xffffffffu, s3, o);
        li = min(li, __shfl_down_sync(0xffffffffu, li, o));
        ri = max(ri, __shfl_down_sync(0xffffffffu, ri, o));
    }
    if (lane == 0) {
        fp1[0][wrp] = s0; fp1[1][wrp] = s1; fp1[2][wrp] = s2; fp1[3][wrp] = s3;
        ip1[0][wrp] = li; ip1[1][wrp] = ri;
    }
    __syncthreads();
    if (wrp < 4) {
        float v = (lane < NWARP) ? fp1[wrp][lane] : 0.0f;
#pragma unroll
        for (int o = 8; o; o >>= 1) v += __shfl_down_sync(0xffffffffu, v, o);
        if (lane == 0) s_S[wrp] = v;
    } else if (wrp == 4) {
        int v = (lane < NWARP) ? ip1[0][lane] : INT_MAX;
#pragma unroll
        for (int o = 8; o; o >>= 1) v = min(v, __shfl_down_sync(0xffffffffu, v, o));
        if (lane == 0) s_lr[0] = v;
    } else if (wrp == 5) {
        int v = (lane < NWARP) ? ip1[1][lane] : INT_MIN;
#pragma unroll
        for (int o = 8; o; o >>= 1) v = max(v, __shfl_down_sync(0xffffffffu, v, o));
        if (lane == 0) s_lr[1] = v;
    }
    __syncthreads();

    // ---- 4096-point Stockham radix-8 FFT, 4 stages, natural-order output ----
    r8_stage<1, true, true>(bufA, bufB, tab, tid);
    __syncthreads();
    r8_stage<8, true, false>(bufB, bufA, tab, tid);
    __syncthreads();
    r8_stage<64, true, false>(bufA, bufB, tab, tid);
    __syncthreads();
    r8_stage<512, false, false>(bufB, bufA, tab, tid);
    __syncthreads();
    const float2* __restrict__ cur = bufA;

    // ---- real-FFT unpack + magnitude sum (Hermitian-halved) ----
    float ms = 0.0f;
#pragma unroll
    for (int k0 = 0; k0 < N2 / NTH; k0++) {
        int k = tid + k0 * NTH;
        int kp = (N2 - k) & (N2 - 1);
        float2 Zk = cur[swz(k)];
        float2 Zp = cur[swz(kp)];
        float Er = 0.5f * (Zk.x + Zp.x);
        float Ei = 0.5f * (Zk.y - Zp.y);
        float Or = 0.5f * (Zk.y + Zp.y);
        float Oi = 0.5f * (Zp.x - Zk.x);
        float2 w;
        if (k0 < 2) {
            float2 t = tab[k];
            w = make_float2(t.x, -t.y);
        } else if (k0 < 4) {
            w = Wq(tab, k);
        } else {
            float2 u = Wq(tab, k - 2048);
            w = make_float2(u.y, -u.x);
        }
        float2 wo = cmul(w, make_float2(Or, Oi));
        if (k == 0) {
            ms += fabsf(Er + Or) + fabsf(Er - Or);  // |X[0]| + |X[4096]|
        } else {
            float xr = Er + wo.x, xi = Ei + wo.y;
            ms += 2.0f * fast_sqrt(fmaf(xr, xr, xi * xi));
        }
    }
#pragma unroll
    for (int o = 16; o; o >>= 1) ms += __shfl_down_sync(0xffffffffu, ms, o);
    if (lane == 0) fp1[0][wrp] = ms;
    __syncthreads();
    if (wrp == 0) {
        float v = (lane < NWARP) ? fp1[0][lane] : 0.0f;
#pragma unroll
        for (int o = 8; o; o >>= 1) v += __shfl_down_sync(0xffffffffu, v, o);
        if (lane == 0) {
            const float hs = 0.5f / SRATE;
            float S_T0 = s_S[0], S_P0 = s_S[1], S_T2 = s_S[2], S_T3 = s_S[3];
            float sig0 = s_pts[0], rT1 = s_pts[1], rT2 = s_pts[2], rT3 = s_pts[3];
            float S_T1 = (P0 > V0) ? (S_P0 - sp0) : S_T0;
            // C(j) = hs * (2*S[j] - sig[j] - sig[0])
            float C_T0 = hs * (2.0f * S_T0 - sv0 - sig0);
            float C_P0 = hs * (2.0f * S_P0 - sp0 - sig0);
            float C_T1 = hs * (2.0f * S_T1 - rT1 - sig0);
            float C_T2 = hs * (2.0f * S_T2 - rT2 - sig0);
            float C_T3 = hs * (2.0f * S_T3 - rT3 - sig0);
            float pa = C_T3 - C_T0;
            float a2 = C_T2 - C_P0;
            float a1 = C_T1 - C_T0;
            int lii = s_lr[0], rii = s_lr[1];
            if (lii == INT_MAX) lii = V0;
            if (rii == -1) rii = P0;
            float pwhh = (float)(rii - lii) * (1.0f / SRATE);

            float fftm = v * (1.0f / (float)LSIG);
            float mean = sum * (1.0f / (float)LSIG);
            float var = (ssq - sum * mean) * (1.0f / (float)(LSIG - 1));
            float* o_ = out + (size_t)blockIdx.x * 10;
            o_[0] = mx;
            o_[1] = mx - mn;
            o_[2] = var;
            o_[3] = sqrtf(var);
            o_[4] = fftm;
            o_[5] = valid ? pa : 0.0f;
            o_[6] = valid ? a2 : 0.0f;
            o_[7] = valid ? PH : 0.0f;
            o_[8] = valid ? a1 : 0.0f;
            o_[9] = valid ? pwhh : 0.0f;
        }
    }
}

extern "C" void kernel_launch(void* const* d_in, const int* in_sizes, int n_in,
                              void* d_out, int out_size) {
    const float* x = (const float*)d_in[0];
    float* out = (float*)d_out;
    int nrow = in_sizes[0] / LSIG;

    (void)n_in; (void)out_size;

    const int smem = (2 * N2 + 1025) * (int)sizeof(float2);  // 73736
    cudaFuncSetAttribute(feat_kernel, cudaFuncAttributeMaxDynamicSharedMemorySize, smem);

    tab_init_kernel<<<5, 256>>>();
    feat_kernel<<<nrow, NTH, smem>>>(x, out);
}

// round 17
// speedup vs baseline: 1.1070x; 1.1032x over previous
#include <cuda_runtime.h>
#include <math.h>
#include <float.h>
#include <limits.h>

#define LSIG 8192
#define N2   4096
#define NTH  512
#define NWARP 16
#define SRATE 30.0f

// quarter-wave table: (cos, sin)(2*pi*k/8192) for k = 0..1024
__device__ float2 g_tab[1025];

__global__ void tab_init_kernel() {
    int k = blockIdx.x * blockDim.x + threadIdx.x;
    if (k <= 1024) {
        double a = 2.0 * 3.14159265358979323846 * (double)k / 8192.0;
        g_tab[k] = make_float2((float)cos(a), (float)sin(a));
    }
}

// sqrt on the FMA pipe (avoid MUFU bottleneck). Safe at x == 0.
__device__ __forceinline__ float fast_sqrt(float x) {
    float xh = 0.5f * x;
    int i = __float_as_int(x);
    i = 0x5f375a86 - (i >> 1);
    float y = __int_as_float(i);
    y = y * (1.5f - xh * y * y);
    y = y * (1.5f - xh * y * y);
    return x * y;
}

// XOR bank swizzle on complex index (FFT stages only).
__device__ __forceinline__ int swz(int a) { return a ^ ((a >> 4) & 15); }

// e^{-2*pi*i*q/8192} for q in [0, 2048), via quarter-wave table
__device__ __forceinline__ float2 Wq(const float2* __restrict__ tab, int q) {
    if (q <= 1024) {
        float2 t = tab[q];
        return make_float2(t.x, -t.y);
    }
    float2 t = tab[2048 - q];
    return make_float2(t.y, -t.x);
}

__device__ __forceinline__ float2 cmul(float2 a, float2 b) {
    return make_float2(fmaf(a.x, b.x, -(a.y * b.y)), fmaf(a.x, b.y, a.y * b.x));
}
__device__ __forceinline__ float2 cadd(float2 a, float2 b) {
    return make_float2(a.x + b.x, a.y + b.y);
}
__device__ __forceinline__ float2 csub(float2 a, float2 b) {
    return make_float2(a.x - b.x, a.y - b.y);
}
// i * a
__device__ __forceinline__ float2 jmul(float2 a) { return make_float2(-a.y, a.x); }

// One radix-8 Stockham stage. S = 8^t. NATREAD: read natural layout (stage 0).
// TW: apply twiddles (false for last stage where p == 0).
template <int S, bool TW, bool NATREAD>
__device__ __forceinline__ void r8_stage(const float2* __restrict__ cur,
                                         float2* __restrict__ nxt,
                                         const float2* __restrict__ tab,
                                         int i) {
    const int base = NATREAD ? i : swz(i);
    float2 a0 = cur[base];
    float2 a1 = cur[base + 512];
    float2 a2 = cur[base + 1024];
    float2 a3 = cur[base + 1536];
    float2 a4 = cur[base + 2048];
    float2 a5 = cur[base + 2560];
    float2 a6 = cur[base + 3072];
    float2 a7 = cur[base + 3584];

    float2 ta = cadd(a0, a4), tb = csub(a0, a4);
    float2 tc = cadd(a2, a6), td = jmul(csub(a2, a6));
    float2 E0 = cadd(ta, tc);
    float2 E1 = csub(tb, td);
    float2 E2 = csub(ta, tc);
    float2 E3 = cadd(tb, td);
    ta = cadd(a1, a5); tb = csub(a1, a5);
    tc = cadd(a3, a7); td = jmul(csub(a3, a7));
    float2 O0 = cadd(ta, tc);
    float2 O1 = csub(tb, td);
    float2 O2 = csub(ta, tc);
    float2 O3 = cadd(tb, td);

    const float C = 0.70710678118654752f;
    float2 R1 = make_float2(C * (O1.x + O1.y), C * (O1.y - O1.x));
    float2 R2 = make_float2(O2.y, -O2.x);
    float2 R3 = make_float2(C * (O3.y - O3.x), -C * (O3.x + O3.y));

    if (TW) {
        const int ps = i & ~(S - 1);
        const int wb = i + 7 * ps;
        float2 t1 = tab[ps << 1];
        float2 w1 = make_float2(t1.x, -t1.y);
        float2 w2 = cmul(w1, w1);
        float2 w4 = cmul(w2, w2);

        nxt[swz(wb)] = cadd(E0, O0);
        nxt[swz(wb + 4 * S)] = cmul(w4, csub(E0, O0));
        float2 wr = w1;
        nxt[swz(wb + S)] = cmul(wr, cadd(E1, R1));
        nxt[swz(wb + 5 * S)] = cmul(cmul(wr, w4), csub(E1, R1));
        wr = w2;
        nxt[swz(wb + 2 * S)] = cmul(wr, cadd(E2, R2));
        nxt[swz(wb + 6 * S)] = cmul(cmul(wr, w4), csub(E2, R2));
        wr = cmul(w2, w1);
        nxt[swz(wb + 3 * S)] = cmul(wr, cadd(E3, R3));
        nxt[swz(wb + 7 * S)] = cmul(cmul(wr, w4), csub(E3, R3));
    } else {
        const int sb = swz(i);
        nxt[sb] = cadd(E0, O0);
        nxt[sb + 512] = cadd(E1, R1);
        nxt[sb + 1024] = cadd(E2, R2);
        nxt[sb + 1536] = cadd(E3, R3);
        nxt[sb + 2048] = csub(E0, O0);
        nxt[sb + 2560] = csub(E1, R1);
        nxt[sb + 3072] = csub(E2, R2);
        nxt[sb + 3584] = csub(E3, R3);
    }
}

// two-smallest insertion (order-insensitive)
#define INS2(va, vb, idx)                         \
    do {                                          \
        if ((idx) < (va)) { (vb) = (va); (va) = (idx); } \
        else if ((idx) < (vb)) (vb) = (idx);      \
    } while (0)

// prefix-masked block sum: add elements of 4-block q (indices base..base+3) with idx <= T
#define PSUM(T, s)                                \
    do {                                          \
        if (base + 3 <= (T)) (s) += bs;           \
        else if (base <= (T)) {                   \
            (s) += q.x;                           \
            if (base + 1 <= (T)) (s) += q.y;      \
            if (base + 2 <= (T)) (s) += q.z;      \
        }                                         \
    } while (0)

// dynamic smem: bufA[4096] | bufB[4096] | tab[1025]  (float2) = 73736 bytes
extern __shared__ float2 s_dyn2[];

__global__ __launch_bounds__(NTH, 3)
void feat_kernel(const float* __restrict__ x, float* __restrict__ out) {
    float2* bufA = s_dyn2;
    float2* bufB = s_dyn2 + N2;
    float2* tab = s_dyn2 + 2 * N2;

    __shared__ float fp1[4][NWARP];
    __shared__ int ip1[6][NWARP];
    __shared__ float fres[4];
    __shared__ int ires[6];
    __shared__ float s_S[4];
    __shared__ int s_lr[2];
    __shared__ float s_pts[4];

    const int tid = threadIdx.x;
    const int lane = tid & 31;
    const int wrp = tid >> 5;
    const float* __restrict__ xg = x + (size_t)blockIdx.x * LSIG;
    const float2* __restrict__ sig2 = (const float2*)xg;

#pragma unroll
    for (int i = tid; i < 1025; i += NTH) tab[i] = g_tab[i];

    // ---- fused pass: global load + stats + interior peak/valley ----
    float mx = -FLT_MAX, mn = FLT_MAX, sum = 0.0f, ssq = 0.0f;
    int np = 0, nv = 0, p0 = INT_MAX, va = INT_MAX, vb = INT_MAX, vlast = -1;
#pragma unroll
    for (int k = 0; k < N2 / NTH; k++) {
        int n = tid + k * NTH;
        float2 v = sig2[n];
        mx = fmaxf(mx, fmaxf(v.x, v.y));
        mn = fminf(mn, fminf(v.x, v.y));
        sum += v.x + v.y;
        ssq = fmaf(v.x, v.x, ssq);
        ssq = fmaf(v.y, v.y, ssq);
        bufA[n] = v;
        float pl = __shfl_up_sync(0xffffffffu, v.y, 1);
        float nr = __shfl_down_sync(0xffffffffu, v.x, 1);
        int ie = 2 * n, io = ie + 1;
        bool de = (lane != 0) && (n > 0);
        bool dq = (lane != 31) && (n < N2 - 1);
        if (de && v.x > pl && v.x > v.y) { np++; p0 = min(p0, ie); }
        if (de && v.x < pl && v.x < v.y) { nv++; vlast = max(vlast, ie); INS2(va, vb, ie); }
        if (dq && v.y > v.x && v.y > nr) { np++; p0 = min(p0, io); }
        if (dq && v.y < v.x && v.y < nr) { nv++; vlast = max(vlast, io); INS2(va, vb, io); }
    }

    // ---- warp-boundary fix-up, parallelized across threads, via global (L2-hot) ----
    // E-type (lane0 cases): ie = 64*m, m = 1..127. O-type (lane31): io = 64*m+63, m = 0..126.
    {
        int idx = -1;
        if (tid >= 1 && tid <= 127) idx = tid << 6;
        else if (tid >= 256 && tid <= 382) idx = ((tid - 256) << 6) + 63;
        if (idx > 0) {
            float a = __ldg(xg + idx - 1);
            float v = __ldg(xg + idx);
            float c = __ldg(xg + idx + 1);
            if (v > a && v > c) { np++; p0 = min(p0, idx); }
            if (v < a && v < c) { nv++; vlast = max(vlast, idx); INS2(va, vb, idx); }
        }
    }
    __syncthreads();

    const float* __restrict__ re = (const float*)bufA;

    // ---- batched block reduction: all phase-1 quantities, 2 barriers ----
#pragma unroll
    for (int o = 16; o; o >>= 1) {
        mx = fmaxf(mx, __shfl_down_sync(0xffffffffu, mx, o));
        mn = fminf(mn, __shfl_down_sync(0xffffffffu, mn, o));
        sum += __shfl_down_sync(0xffffffffu, sum, o);
        ssq += __shfl_down_sync(0xffffffffu, ssq, o);
        np += __shfl_down_sync(0xffffffffu, np, o);
        nv += __shfl_down_sync(0xffffffffu, nv, o);
        p0 = min(p0, __shfl_down_sync(0xffffffffu, p0, o));
        vlast = max(vlast, __shfl_down_sync(0xffffffffu, vlast, o));
        int oa = __shfl_down_sync(0xffffffffu, va, o);
        int ob = __shfl_down_sync(0xffffffffu, vb, o);
        int m1 = min(va, oa);
        vb = min(max(va, oa), min(vb, ob));
        va = m1;
    }
    if (lane == 0) {
        fp1[0][wrp] = mx; fp1[1][wrp] = mn; fp1[2][wrp] = sum; fp1[3][wrp] = ssq;
        ip1[0][wrp] = np; ip1[1][wrp] = nv; ip1[2][wrp] = p0; ip1[3][wrp] = vlast;
        ip1[4][wrp] = va; ip1[5][wrp] = vb;
    }
    __syncthreads();
    if (wrp < 4) {
        float ident = (wrp == 0) ? -FLT_MAX : (wrp == 1) ? FLT_MAX : 0.0f;
        float v = (lane < NWARP) ? fp1[wrp][lane] : ident;
#pragma unroll
        for (int o = 8; o; o >>= 1) {
            float ov = __shfl_down_sync(0xffffffffu, v, o);
            v = (wrp == 0) ? fmaxf(v, ov) : (wrp == 1) ? fminf(v, ov) : (v + ov);
        }
        if (lane == 0) fres[wrp] = v;
    } else if (wrp < 8) {
        int q = wrp - 4;  // 0:np 1:nv 2:p0(min) 3:vlast(max)
        int ident = (q < 2) ? 0 : (q == 2) ? INT_MAX : INT_MIN;
        int v = (lane < NWARP) ? ip1[q][lane] : ident;
#pragma unroll
        for (int o = 8; o; o >>= 1) {
            int ov = __shfl_down_sync(0xffffffffu, v, o);
            v = (q < 2) ? (v + ov) : (q == 2) ? min(v, ov) : max(v, ov);
        }
        if (lane == 0) ires[q] = v;
    } else if (wrp == 8) {
        int a = (lane < NWARP) ? ip1[4][lane] : INT_MAX;
        int b = (lane < NWARP) ? ip1[5][lane] : INT_MAX;
#pragma unroll
        for (int o = 8; o; o >>= 1) {
            int oa = __shfl_down_sync(0xffffffffu, a, o);
            int ob = __shfl_down_sync(0xffffffffu, b, o);
            int m1 = min(a, oa);
            b = min(max(a, oa), min(b, ob));
            a = m1;
        }
        if (lane == 0) { ires[4] = a; ires[5] = b; }
    }
    __syncthreads();
    mx = fres[0]; mn = fres[1]; sum = fres[2]; ssq = fres[3];
    np = ires[0]; nv = ires[1]; p0 = ires[2]; vlast = ires[3];
    va = ires[4]; vb = ires[5];

    const bool valid = (np >= 1) && (nv >= 2);
    const int P0 = valid ? p0 : 0;
    const int V0 = valid ? va : 0;
    const int V1 = valid ? vb : 0;
    const int VL = valid ? vlast : 0;

    const float sp0 = re[P0], sv0 = re[V0];
    const float PH = sp0 - sv0;
    const float hh = (PH + sv0) * 0.5f;

    const int T2 = max(V1 - 1, P0);
    const int T3 = max(VL - 1, V0);
    if (tid == 0) {
        s_pts[0] = re[0];
        s_pts[1] = re[max(P0 - 1, V0)];  // sig[T1]
        s_pts[2] = re[T2];
        s_pts[3] = re[T3];
    }

    // ---- phase 2: block-granular masked prefix sums + half-height width ----
    float s0 = 0.0f, s1 = 0.0f, s2 = 0.0f, s3 = 0.0f;
    int li = INT_MAX, ri = -1;
    {
        const float4* __restrict__ b4 = (const float4*)bufA;
#pragma unroll
        for (int k = 0; k < 4; k++) {
            int t = tid + k * NTH;
            float4 q = b4[t];
            int base = 4 * t;
            float bs = (q.x + q.y) + (q.z + q.w);
            PSUM(V0, s0);
            PSUM(P0, s1);
            PSUM(T2, s2);
            PSUM(T3, s3);
            // half-height window: only blocks intersecting [V0, P0]
            if (base <= P0 && base + 3 >= V0) {
#pragma unroll
                for (int j = 0; j < 4; j++) {
                    int idx = base + j;
                    float val = (j == 0) ? q.x : (j == 1) ? q.y : (j == 2) ? q.z : q.w;
                    if (val >= hh) {
                        if (idx >= V0 && idx < P0) li = min(li, idx);
                        if (idx > V0 && idx <= P0) ri = max(ri, idx);
                    }
                }
            }
        }
    }
    // reduce phase-2 quantities now (frees registers before FFT)
#pragma unroll
    for (int o = 16; o; o >>= 1) {
        s0 += __shfl_down_sync(0xffffffffu, s0, o);
        s1 += __shfl_down_sync(0xffffffffu, s1, o);
        s2 += __shfl_down_sync(0xffffffffu, s2, o);
        s3 += __shfl_down_sync(0xffffffffu, s3, o);
        li = min(li, __shfl_down_sync(0xffffffffu, li, o));
        ri = max(ri, __shfl_down_sync(0xffffffffu, ri, o));
    }
    if (lane == 0) {
        fp1[0][wrp] = s0; fp1[1][wrp] = s1; fp1[2][wrp] = s2; fp1[3][wrp] = s3;
        ip1[0][wrp] = li; ip1[1][wrp] = ri;
    }
    __syncthreads();
    if (wrp < 4) {
        float v = (lane < NWARP) ? fp1[wrp][lane] : 0.0f;
#pragma unroll
        for (int o = 8; o; o >>= 1) v += __shfl_down_sync(0xffffffffu, v, o);
        if (lane == 0) s_S[wrp] = v;
    } else if (wrp == 4) {
        int v = (lane < NWARP) ? ip1[0][lane] : INT_MAX;
#pragma unroll
        for (int o = 8; o; o >>= 1) v = min(v, __shfl_down_sync(0xffffffffu, v, o));
        if (lane == 0) s_lr[0] = v;
    } else if (wrp == 5) {
        int v = (lane < NWARP) ? ip1[1][lane] : INT_MIN;
#pragma unroll
        for (int o = 8; o; o >>= 1) v = max(v, __shfl_down_sync(0xffffffffu, v, o));
        if (lane == 0) s_lr[1] = v;
    }
    __syncthreads();

    // ---- 4096-point Stockham radix-8 FFT, 4 stages, natural-order output ----
    r8_stage<1, true, true>(bufA, bufB, tab, tid);
    __syncthreads();
    r8_stage<8, true, false>(bufB, bufA, tab, tid);
    __syncthreads();
    r8_stage<64, true, false>(bufA, bufB, tab, tid);
    __syncthreads();
    r8_stage<512, false, false>(bufB, bufA, tab, tid);
    __syncthreads();
    const float2* __restrict__ cur = bufA;

    // ---- real-FFT unpack, pair-halved: k in [0,2048) gives |X[k]| and |X[4096-k]| ----
    // total = |X0| + |X4096| + 2*( sum_{k=1..2047} (|X[k]|+|X[4096-k]|) + |Z[2048]| )
    float ms = 0.0f;
#pragma unroll
    for (int k0 = 0; k0 < 4; k0++) {
        int k = tid + k0 * NTH;
        int kp = (N2 - k) & (N2 - 1);
        float2 Zk = cur[swz(k)];
        float2 Zp = cur[swz(kp)];
        float Er = 0.5f * (Zk.x + Zp.x);
        float Ei = 0.5f * (Zk.y - Zp.y);
        float Or = 0.5f * (Zk.y + Zp.y);
        float Oi = 0.5f * (Zp.x - Zk.x);
        float2 w;
        if (k0 < 2) {  // k <= 1023: quarter table direct
            float2 t = tab[k];
            w = make_float2(t.x, -t.y);
        } else {       // k in [1024, 2048)
            float2 t = tab[2048 - k];
            w = make_float2(t.y, -t.x);
        }
        float2 wo = cmul(w, make_float2(Or, Oi));
        float xr = Er + wo.x, xi = Ei + wo.y;
        float yr = Er - wo.x, yi = Ei - wo.y;
        if (k == 0) {
            // xr = X[0], yr = X[4096] (both real); plus uncovered bin 2048
            float2 Zm = cur[swz(2048)];
            ms += fabsf(xr) + fabsf(yr) +
                  2.0f * fast_sqrt(fmaf(Zm.x, Zm.x, Zm.y * Zm.y));
        } else {
            ms += 2.0f * (fast_sqrt(fmaf(xr, xr, xi * xi)) +
                          fast_sqrt(fmaf(yr, yr, yi * yi)));
        }
    }
#pragma unroll
    for (int o = 16; o; o >>= 1) ms += __shfl_down_sync(0xffffffffu, ms, o);
    if (lane == 0) fp1[0][wrp] = ms;
    __syncthreads();
    if (wrp == 0) {
        float v = (lane < NWARP) ? fp1[0][lane] : 0.0f;
#pragma unroll
        for (int o = 8; o; o >>= 1) v += __shfl_down_sync(0xffffffffu, v, o);
        if (lane == 0) {
            const float hs = 0.5f / SRATE;
            float S_T0 = s_S[0], S_P0 = s_S[1], S_T2 = s_S[2], S_T3 = s_S[3];
            float sig0 = s_pts[0], rT1 = s_pts[1], rT2 = s_pts[2], rT3 = s_pts[3];
            float S_T1 = (P0 > V0) ? (S_P0 - sp0) : S_T0;
            // C(j) = hs * (2*S[j] - sig[j] - sig[0])
            float C_T0 = hs * (2.0f * S_T0 - sv0 - sig0);
            float C_P0 = hs * (2.0f * S_P0 - sp0 - sig0);
            float C_T1 = hs * (2.0f * S_T1 - rT1 - sig0);
            float C_T2 = hs * (2.0f * S_T2 - rT2 - sig0);
            float C_T3 = hs * (2.0f * S_T3 - rT3 - sig0);
            float pa = C_T3 - C_T0;
            float a2 = C_T2 - C_P0;
            float a1 = C_T1 - C_T0;
            int lii = s_lr[0], rii = s_lr[1];
            if (lii == INT_MAX) lii = V0;
            if (rii == -1) rii = P0;
            float pwhh = (float)(rii - lii) * (1.0f / SRATE);

            float fftm = v * (1.0f / (float)LSIG);
            float mean = sum * (1.0f / (float)LSIG);
            float var = (ssq - sum * mean) * (1.0f / (float)(LSIG - 1));
            float* o_ = out + (size_t)blockIdx.x * 10;
            o_[0] = mx;
            o_[1] = mx - mn;
            o_[2] = var;
            o_[3] = sqrtf(var);
            o_[4] = fftm;
            o_[5] = valid ? pa : 0.0f;
            o_[6] = valid ? a2 : 0.0f;
            o_[7] = valid ? PH : 0.0f;
            o_[8] = valid ? a1 : 0.0f;
            o_[9] = valid ? pwhh : 0.0f;
        }
    }
}

extern "C" void kernel_launch(void* const* d_in, const int* in_sizes, int n_in,
                              void* d_out, int out_size) {
    const float* x = (const float*)d_in[0];
    float* out = (float*)d_out;
    int nrow = in_sizes[0] / LSIG;

    (void)n_in; (void)out_size;

    const int smem = (2 * N2 + 1025) * (int)sizeof(float2);  // 73736
    cudaFuncSetAttribute(feat_kernel, cudaFuncAttributeMaxDynamicSharedMemorySize, smem);

    tab_init_kernel<<<5, 256>>>();
    feat_kernel<<<nrow, NTH, smem>>>(x, out);
}